// round 2
// baseline (speedup 1.0000x reference)
#include <cuda_runtime.h>

// Problem constants
#define BB 32
#define TT 1024
#define DKK 64
#define TQ 32          // query rows per CTA
#define KC 128         // K/V rows per chunk
#define NTHREADS 256
#define SS_STRIDE 1028 // padded score row stride (floats)
#define KV_STRIDE 68   // padded K/V row stride (floats) = 17 float4
#define Q_STRIDE  68

#define MASK_FILL_F (-4294967295.0f) // -2^32 + 1

__global__ __launch_bounds__(NTHREADS, 1)
void mha_kernel(const float* __restrict__ Kg,
                const float* __restrict__ Vg,
                const float* __restrict__ Qg,
                const int* __restrict__ Mg,     // bool promoted to 4-byte: nonzero == masked
                const float* __restrict__ QMg,
                float* __restrict__ Og,   // [B,T,DK]
                float* __restrict__ Ag)   // [B,T,T]
{
    extern __shared__ float smem[];
    float* sQ  = smem;                         // TQ * Q_STRIDE
    float* sS  = sQ + TQ * Q_STRIDE;           // TQ * SS_STRIDE
    float* sKV = sS + TQ * SS_STRIDE;          // KC * KV_STRIDE

    const int b  = blockIdx.y;
    const int q0 = blockIdx.x * TQ;
    const int t  = threadIdx.x;

    // ---- Load Q tile: TQ x DK = 512 float4, 2 per thread ----
    {
        const float4* Qg4 = (const float4*)(Qg + ((size_t)b * TT + q0) * DKK);
        float4* sQ4w = (float4*)sQ;
        #pragma unroll
        for (int i = 0; i < 2; i++) {
            int idx = t + i * NTHREADS;        // 0..511
            int row = idx >> 4, col = idx & 15;
            sQ4w[row * (Q_STRIDE / 4) + col] = Qg4[row * 16 + col];
        }
    }
    __syncthreads();

    const float scale = 0.125f; // 1/sqrt(64)
    const int qg = t >> 5;      // 0..7  -> 4 q rows each
    const int kg = t & 31;      // 0..31 -> k = kg + 32*j, j=0..3

    const float4* sQ4  = (const float4*)sQ;
    const float4* sKV4 = (const float4*)sKV;

    // ---- Phase 1: scores S = mask(QK^T/8) into sS ----
    for (int c = 0; c < TT / KC; ++c) {
        // load K chunk: KC x DK = 2048 float4, 8 per thread
        {
            const float4* Kg4 = (const float4*)(Kg + ((size_t)b * TT + c * KC) * DKK);
            float4* sKV4w = (float4*)sKV;
            #pragma unroll
            for (int i = 0; i < 8; i++) {
                int idx = t + i * NTHREADS;    // 0..2047
                int row = idx >> 4, col = idx & 15;
                sKV4w[row * (KV_STRIDE / 4) + col] = Kg4[row * 16 + col];
            }
        }
        __syncthreads();

        float acc[4][4];
        #pragma unroll
        for (int i = 0; i < 4; i++)
            #pragma unroll
            for (int j = 0; j < 4; j++)
                acc[i][j] = 0.0f;

        #pragma unroll
        for (int d4 = 0; d4 < DKK / 4; d4++) {
            float4 a[4], bv[4];
            #pragma unroll
            for (int i = 0; i < 4; i++)
                a[i] = sQ4[(qg * 4 + i) * (Q_STRIDE / 4) + d4];      // broadcast
            #pragma unroll
            for (int j = 0; j < 4; j++)
                bv[j] = sKV4[(kg + 32 * j) * (KV_STRIDE / 4) + d4];  // conflict-free
            #pragma unroll
            for (int i = 0; i < 4; i++)
                #pragma unroll
                for (int j = 0; j < 4; j++)
                    acc[i][j] += a[i].x * bv[j].x + a[i].y * bv[j].y
                               + a[i].z * bv[j].z + a[i].w * bv[j].w;
        }

        // apply mask + scale, store to sS
        #pragma unroll
        for (int i = 0; i < 4; i++) {
            int lq = qg * 4 + i;
            const int* mrow = Mg + ((size_t)b * TT + q0 + lq) * TT;
            #pragma unroll
            for (int j = 0; j < 4; j++) {
                int kk = c * KC + kg + 32 * j;
                float v = acc[i][j] * scale;
                if (mrow[kk] != 0) v = MASK_FILL_F;
                sS[lq * SS_STRIDE + kk] = v;
            }
        }
        __syncthreads();
    }

    // ---- Phase 2: softmax per row (warp per row-group), write attn ----
    {
        const int w = t >> 5, lane = t & 31;
        const float4* sS4 = (const float4*)sS;
        float4* sS4w = (float4*)sS;
        #pragma unroll
        for (int r = 0; r < 4; r++) {
            int row = w * 4 + r;
            float4 v[8];
            #pragma unroll
            for (int i = 0; i < 8; i++)
                v[i] = sS4[row * (SS_STRIDE / 4) + lane + 32 * i];
            float mx = -3.4e38f;
            #pragma unroll
            for (int i = 0; i < 8; i++) {
                mx = fmaxf(mx, fmaxf(fmaxf(v[i].x, v[i].y), fmaxf(v[i].z, v[i].w)));
            }
            #pragma unroll
            for (int o = 16; o > 0; o >>= 1)
                mx = fmaxf(mx, __shfl_xor_sync(0xFFFFFFFFu, mx, o));
            float sum = 0.0f;
            #pragma unroll
            for (int i = 0; i < 8; i++) {
                v[i].x = __expf(v[i].x - mx);
                v[i].y = __expf(v[i].y - mx);
                v[i].z = __expf(v[i].z - mx);
                v[i].w = __expf(v[i].w - mx);
                sum += v[i].x + v[i].y + v[i].z + v[i].w;
            }
            #pragma unroll
            for (int o = 16; o > 0; o >>= 1)
                sum += __shfl_xor_sync(0xFFFFFFFFu, sum, o);
            float f = QMg[(size_t)b * TT + q0 + row] / sum;
            float4* Ag4 = (float4*)(Ag + ((size_t)b * TT + q0 + row) * TT);
            #pragma unroll
            for (int i = 0; i < 8; i++) {
                v[i].x *= f; v[i].y *= f; v[i].z *= f; v[i].w *= f;
                sS4w[row * (SS_STRIDE / 4) + lane + 32 * i] = v[i];
                Ag4[lane + 32 * i] = v[i];
            }
        }
    }

    // ---- Phase 3: result = P @ V ----
    {
        const int tq = t >> 4;       // 0..15 -> 2 q rows each
        const int lq = tq * 2;
        const int td = t & 15;       // float4 column in D
        float4 acc0 = make_float4(0.f, 0.f, 0.f, 0.f);
        float4 acc1 = make_float4(0.f, 0.f, 0.f, 0.f);

        for (int c = 0; c < TT / KC; ++c) {
            __syncthreads(); // previous chunk compute done / softmax done
            {
                const float4* Vg4 = (const float4*)(Vg + ((size_t)b * TT + c * KC) * DKK);
                float4* sKV4w = (float4*)sKV;
                #pragma unroll
                for (int i = 0; i < 8; i++) {
                    int idx = t + i * NTHREADS;
                    int row = idx >> 4, col = idx & 15;
                    sKV4w[row * (KV_STRIDE / 4) + col] = Vg4[row * 16 + col];
                }
            }
            __syncthreads();

            const float* p0row = sS + lq * SS_STRIDE + c * KC;
            const float* p1row = sS + (lq + 1) * SS_STRIDE + c * KC;
            #pragma unroll 4
            for (int k = 0; k < KC; k++) {
                float p0 = p0row[k];
                float p1 = p1row[k];
                float4 vv = sKV4[k * (KV_STRIDE / 4) + td];
                acc0.x += p0 * vv.x; acc0.y += p0 * vv.y;
                acc0.z += p0 * vv.z; acc0.w += p0 * vv.w;
                acc1.x += p1 * vv.x; acc1.y += p1 * vv.y;
                acc1.z += p1 * vv.z; acc1.w += p1 * vv.w;
            }
        }

        float4* Og4 = (float4*)(Og + ((size_t)b * TT + q0) * DKK);
        Og4[lq * 16 + td] = acc0;
        Og4[(lq + 1) * 16 + td] = acc1;
    }
}

extern "C" void kernel_launch(void* const* d_in, const int* in_sizes, int n_in,
                              void* d_out, int out_size) {
    // Identify inputs by element count (robust to input-ordering convention):
    //   mask       = B*T*T  = 33,554,432
    //   query_mask = B*T    = 32,768
    //   K/V/Q      = B*T*DK = 2,097,152 each
    int mask_i = 3, qm_i = 4;
    for (int i = 0; i < n_in; i++) {
        if (in_sizes[i] == BB * TT * TT)      mask_i = i;
        else if (in_sizes[i] == BB * TT)      qm_i = i;
    }
    int k_i = 0, v_i = 1, q_i = 2;
    if (mask_i == 1 && qm_i == 3) {           // alphabetical: key, mask, query, query_mask, value
        k_i = 0; q_i = 2; v_i = 4;
    }

    const float* Kg  = (const float*)d_in[k_i];
    const float* Vg  = (const float*)d_in[v_i];
    const float* Qg  = (const float*)d_in[q_i];
    const int*   Mg  = (const int*)d_in[mask_i];   // bool promoted to 4-byte dtype
    const float* QMg = (const float*)d_in[qm_i];

    float* Og = (float*)d_out;                         // result [B,T,DK]
    float* Ag = (float*)d_out + (size_t)BB * TT * DKK; // attn   [B,T,T]

    const int smem_bytes = (TQ * Q_STRIDE + TQ * SS_STRIDE + KC * KV_STRIDE) * (int)sizeof(float);
    cudaFuncSetAttribute(mha_kernel, cudaFuncAttributeMaxDynamicSharedMemorySize, smem_bytes);

    dim3 grid(TT / TQ, BB);
    mha_kernel<<<grid, NTHREADS, smem_bytes>>>(Kg, Vg, Qg, Mg, QMg, Og, Ag);
}

// round 5
// speedup vs baseline: 2.3042x; 2.3042x over previous
#include <cuda_runtime.h>
#include <cuda_bf16.h>
#include <cstdint>

#define BB 32
#define TT 1024
#define DKK 64
#define QTILE 64
#define KCH 128
#define NCHUNK (TT / KCH)
#define NTH 128

#define STRB 144                          // bf16 row stride bytes (72 elems)
#define OFF_QH 0
#define OFF_QL (OFF_QH + 64 * STRB)
#define OFF_KH (OFF_QL + 64 * STRB)
#define OFF_KL (OFF_KH + 128 * STRB)
#define OFF_VH (OFF_KL + 128 * STRB)
#define OFF_VL (OFF_VH + 128 * STRB)
#define SMEM_TOTAL (OFF_VL + 128 * STRB)  // 92160 bytes

__device__ __forceinline__ uint32_t smem_u32(const void* p) {
    uint32_t a;
    asm("{ .reg .u64 t; cvta.to.shared.u64 t, %1; cvt.u32.u64 %0, t; }" : "=r"(a) : "l"(p));
    return a;
}
__device__ __forceinline__ void ldsm4(uint32_t* r, uint32_t a) {
    asm volatile("ldmatrix.sync.aligned.m8n8.x4.shared.b16 {%0,%1,%2,%3}, [%4];"
                 : "=r"(r[0]), "=r"(r[1]), "=r"(r[2]), "=r"(r[3]) : "r"(a));
}
__device__ __forceinline__ void ldsm4t(uint32_t* r, uint32_t a) {
    asm volatile("ldmatrix.sync.aligned.m8n8.x4.trans.shared.b16 {%0,%1,%2,%3}, [%4];"
                 : "=r"(r[0]), "=r"(r[1]), "=r"(r[2]), "=r"(r[3]) : "r"(a));
}
__device__ __forceinline__ void mma16816(float* d, const uint32_t* a, uint32_t b0, uint32_t b1) {
    asm volatile("mma.sync.aligned.m16n8k16.row.col.f32.bf16.bf16.f32 "
                 "{%0,%1,%2,%3}, {%4,%5,%6,%7}, {%8,%9}, {%0,%1,%2,%3};"
                 : "+f"(d[0]), "+f"(d[1]), "+f"(d[2]), "+f"(d[3])
                 : "r"(a[0]), "r"(a[1]), "r"(a[2]), "r"(a[3]), "r"(b0), "r"(b1));
}
__device__ __forceinline__ uint32_t b2u(__nv_bfloat162 h) { return *reinterpret_cast<uint32_t*>(&h); }
__device__ __forceinline__ void split2(float a, float b, uint32_t& h, uint32_t& l) {
    __nv_bfloat162 hh = __floats2bfloat162_rn(a, b);
    float ra = __bfloat162float(hh.x), rb = __bfloat162float(hh.y);
    __nv_bfloat162 ll = __floats2bfloat162_rn(a - ra, b - rb);
    h = b2u(hh); l = b2u(ll);
}

__global__ __launch_bounds__(NTH, 2)
void mha_mma(const float* __restrict__ Kg, const float* __restrict__ Vg,
             const float* __restrict__ Qg, const int* __restrict__ Mg,
             const float* __restrict__ QMg,
             float* __restrict__ Og, float* __restrict__ Ag)
{
    extern __shared__ char smem[];
    __shared__ float frow[QTILE];
    const uint32_t sb = smem_u32(smem);
    const int t = threadIdx.x;
    const int w = t >> 5, lane = t & 31;
    const int qr = w * 16;
    const int bb = blockIdx.y, q0 = blockIdx.x * QTILE;

    // ---- Load Q tile once (bf16 hi/lo) ----
    {
        const float4* Qg4 = (const float4*)(Qg + (size_t)(bb * TT + q0) * DKK);
        #pragma unroll
        for (int i = 0; i < 8; i++) {
            int idx = t + i * NTH;                // 0..1023
            int row = idx >> 4, c4 = idx & 15;
            float4 v = Qg4[idx];
            uint2 h, l;
            split2(v.x, v.y, h.x, l.x);
            split2(v.z, v.w, h.y, l.y);
            *(uint2*)(smem + OFF_QH + row * STRB + c4 * 8) = h;
            *(uint2*)(smem + OFF_QL + row * STRB + c4 * 8) = l;
        }
    }
    __syncthreads();

    // ---- Preload Q A-fragments (loop-invariant) ----
    uint32_t qa_h[4][4], qa_l[4][4];
    {
        uint32_t abase = sb + OFF_QH + (qr + (lane & 15)) * STRB + (lane >> 4) * 16;
        #pragma unroll
        for (int s = 0; s < 4; s++) {
            ldsm4(qa_h[s], abase + s * 32);
            ldsm4(qa_l[s], abase + s * 32 + (OFF_QL - OFF_QH));
        }
    }

    const int r0 = lane >> 2;                     // fragment row 0..7
    const size_t grow0 = (size_t)(bb * TT + q0 + qr + r0);
    const size_t grow1 = grow0 + 8;
    float O[8][4];
    #pragma unroll
    for (int n = 0; n < 8; n++)
        #pragma unroll
        for (int i = 0; i < 4; i++) O[n][i] = 0.0f;
    float rs0 = 0.0f, rs1 = 0.0f;

    for (int c = 0; c < NCHUNK; c++) {
        __syncthreads();                          // prev chunk compute done
        // ---- load K chunk ----
        {
            const float4* G4 = (const float4*)(Kg + (size_t)(bb * TT + c * KCH) * DKK);
            #pragma unroll
            for (int i = 0; i < 16; i++) {
                int idx = t + i * NTH;            // 0..2047
                int row = idx >> 4, c4 = idx & 15;
                float4 v = G4[idx];
                uint2 h, l;
                split2(v.x, v.y, h.x, l.x);
                split2(v.z, v.w, h.y, l.y);
                *(uint2*)(smem + OFF_KH + row * STRB + c4 * 8) = h;
                *(uint2*)(smem + OFF_KL + row * STRB + c4 * 8) = l;
            }
        }
        // ---- load V chunk (natural [k][d]; trans at ldmatrix) ----
        {
            const float4* G4 = (const float4*)(Vg + (size_t)(bb * TT + c * KCH) * DKK);
            #pragma unroll
            for (int i = 0; i < 16; i++) {
                int idx = t + i * NTH;
                int row = idx >> 4, c4 = idx & 15;
                float4 v = G4[idx];
                uint2 h, l;
                split2(v.x, v.y, h.x, l.x);
                split2(v.z, v.w, h.y, l.y);
                *(uint2*)(smem + OFF_VH + row * STRB + c4 * 8) = h;
                *(uint2*)(smem + OFF_VL + row * STRB + c4 * 8) = l;
            }
        }
        __syncthreads();

        // ---- Phase 1: S tiles + exp/mask/pack, per n8-tile j ----
        uint32_t pa_h[8][4], pa_l[8][4];          // P fragments for PV
        const int* mb0 = Mg + grow0 * TT + c * KCH + (lane & 3) * 2;
        const int* mb1 = Mg + grow1 * TT + c * KCH + (lane & 3) * 2;
        float* ab0 = Ag + grow0 * TT + c * KCH + (lane & 3) * 2;
        float* ab1 = Ag + grow1 * TT + c * KCH + (lane & 3) * 2;

        #pragma unroll
        for (int j = 0; j < 16; j++) {
            float S[4] = {0.f, 0.f, 0.f, 0.f};
            uint32_t bh[8], bl[8];
            uint32_t kb = sb + OFF_KH + (8 * j + (lane & 7)) * STRB + ((lane >> 3) & 3) * 16;
            ldsm4(&bh[0], kb);
            ldsm4(&bh[4], kb + 64);
            ldsm4(&bl[0], kb + (OFF_KL - OFF_KH));
            ldsm4(&bl[4], kb + (OFF_KL - OFF_KH) + 64);
            #pragma unroll
            for (int s = 0; s < 4; s++) {
                mma16816(S, qa_h[s], bh[s * 2], bh[s * 2 + 1]);
                mma16816(S, qa_h[s], bl[s * 2], bl[s * 2 + 1]);
                mma16816(S, qa_l[s], bh[s * 2], bh[s * 2 + 1]);
            }
            // mask + exp + attn write + pack
            int2 m0 = *(const int2*)(mb0 + j * 8);
            int2 m1 = *(const int2*)(mb1 + j * 8);
            float e0 = m0.x ? 0.0f : __expf(S[0] * 0.125f);
            float e1 = m0.y ? 0.0f : __expf(S[1] * 0.125f);
            float e2 = m1.x ? 0.0f : __expf(S[2] * 0.125f);
            float e3 = m1.y ? 0.0f : __expf(S[3] * 0.125f);
            rs0 += e0 + e1; rs1 += e2 + e3;
            *(float2*)(ab0 + j * 8) = make_float2(e0, e1);
            *(float2*)(ab1 + j * 8) = make_float2(e2, e3);
            int s8 = j >> 1, i0 = (j & 1) * 2;
            split2(e0, e1, pa_h[s8][i0], pa_l[s8][i0]);
            split2(e2, e3, pa_h[s8][i0 + 1], pa_l[s8][i0 + 1]);
        }

        // ---- Phase 2: O += P @ V ----
        #pragma unroll
        for (int s = 0; s < 8; s++) {
            uint32_t vb = sb + OFF_VH + (16 * s + (lane & 15)) * STRB + (lane >> 4) * 16;
            #pragma unroll
            for (int m = 0; m < 4; m++) {
                uint32_t vh[4], vl[4];
                ldsm4t(vh, vb + m * 32);
                ldsm4t(vl, vb + m * 32 + (OFF_VL - OFF_VH));
                mma16816(O[2 * m],     pa_h[s], vh[0], vh[1]);
                mma16816(O[2 * m],     pa_h[s], vl[0], vl[1]);
                mma16816(O[2 * m],     pa_l[s], vh[0], vh[1]);
                mma16816(O[2 * m + 1], pa_h[s], vh[2], vh[3]);
                mma16816(O[2 * m + 1], pa_h[s], vl[2], vl[3]);
                mma16816(O[2 * m + 1], pa_l[s], vh[2], vh[3]);
            }
        }
    }

    // ---- row sums (quad reduction), scale factors ----
    rs0 += __shfl_xor_sync(0xFFFFFFFFu, rs0, 1);
    rs0 += __shfl_xor_sync(0xFFFFFFFFu, rs0, 2);
    rs1 += __shfl_xor_sync(0xFFFFFFFFu, rs1, 1);
    rs1 += __shfl_xor_sync(0xFFFFFFFFu, rs1, 2);
    float f0 = QMg[grow0] / rs0;
    float f1 = QMg[grow1] / rs1;

    // ---- O output ----
    {
        float2* o0 = (float2*)(Og + grow0 * DKK + (lane & 3) * 2);
        float2* o1 = (float2*)(Og + grow1 * DKK + (lane & 3) * 2);
        #pragma unroll
        for (int n = 0; n < 8; n++) {
            o0[n * 4] = make_float2(f0 * O[n][0], f0 * O[n][1]);
            o1[n * 4] = make_float2(f1 * O[n][2], f1 * O[n][3]);
        }
    }

    // ---- in-kernel attn rescale (rows are L2-hot) ----
    if ((lane & 3) == 0) {
        frow[qr + r0] = f0;
        frow[qr + r0 + 8] = f1;
    }
    __syncthreads();
    {
        float4* A4 = (float4*)(Ag + ((size_t)bb * TT + q0) * TT);
        #pragma unroll 4
        for (int i = 0; i < 128; i++) {
            int idx = i * NTH + t;                // 0..16383
            float f = frow[idx >> 8];
            float4 v = A4[idx];
            v.x *= f; v.y *= f; v.z *= f; v.w *= f;
            A4[idx] = v;
        }
    }
}

extern "C" void kernel_launch(void* const* d_in, const int* in_sizes, int n_in,
                              void* d_out, int out_size) {
    int mask_i = 3, qm_i = 4;
    for (int i = 0; i < n_in; i++) {
        if (in_sizes[i] == BB * TT * TT) mask_i = i;
        else if (in_sizes[i] == BB * TT) qm_i = i;
    }
    int k_i = 0, v_i = 1, q_i = 2;
    if (mask_i == 1 && qm_i == 3) { k_i = 0; q_i = 2; v_i = 4; }

    const float* Kg  = (const float*)d_in[k_i];
    const float* Vg  = (const float*)d_in[v_i];
    const float* Qg  = (const float*)d_in[q_i];
    const int*   Mg  = (const int*)d_in[mask_i];
    const float* QMg = (const float*)d_in[qm_i];

    float* Og = (float*)d_out;
    float* Ag = (float*)d_out + (size_t)BB * TT * DKK;

    cudaFuncSetAttribute(mha_mma, cudaFuncAttributeMaxDynamicSharedMemorySize, SMEM_TOTAL);
    dim3 grid(TT / QTILE, BB);
    mha_mma<<<grid, NTH, SMEM_TOTAL>>>(Kg, Vg, Qg, Mg, QMg, Og, Ag);
}

// round 6
// speedup vs baseline: 2.4262x; 1.0529x over previous
#include <cuda_runtime.h>
#include <cuda_bf16.h>
#include <cstdint>

#define BB 32
#define TT 1024
#define DKK 64
#define QTILE 64
#define KCH 64
#define NCHUNK (TT / KCH)
#define NTH 128

// SMEM layout (dynamic): Q hi/lo, then 2 stages x {KH,KL,VH,VL} of 64x128B each
#define OFF_Q    0
#define OFF_QLO  (OFF_Q + 8192)
#define OFF_ST0  16384
#define STAGE_SZ 32768                 // 4 bufs x 8192
#define BUF_SZ   8192
#define SMEM_TOTAL (OFF_ST0 + 2 * STAGE_SZ)   // 81920

// Prepass scratch: bf16 hi/lo for K and V, [b][t][d] rows of 64 bf16 = 128B
__device__ __align__(16) __nv_bfloat16 gKH[BB * TT * DKK];
__device__ __align__(16) __nv_bfloat16 gKL[BB * TT * DKK];
__device__ __align__(16) __nv_bfloat16 gVH[BB * TT * DKK];
__device__ __align__(16) __nv_bfloat16 gVL[BB * TT * DKK];

__device__ __forceinline__ uint32_t smem_u32(const void* p) {
    uint32_t a;
    asm("{ .reg .u64 t; cvta.to.shared.u64 t, %1; cvt.u32.u64 %0, t; }" : "=r"(a) : "l"(p));
    return a;
}
__device__ __forceinline__ void ldsm4(uint32_t* r, uint32_t a) {
    asm volatile("ldmatrix.sync.aligned.m8n8.x4.shared.b16 {%0,%1,%2,%3}, [%4];"
                 : "=r"(r[0]), "=r"(r[1]), "=r"(r[2]), "=r"(r[3]) : "r"(a));
}
__device__ __forceinline__ void ldsm4t(uint32_t* r, uint32_t a) {
    asm volatile("ldmatrix.sync.aligned.m8n8.x4.trans.shared.b16 {%0,%1,%2,%3}, [%4];"
                 : "=r"(r[0]), "=r"(r[1]), "=r"(r[2]), "=r"(r[3]) : "r"(a));
}
__device__ __forceinline__ void mma16816(float* d, const uint32_t* a, uint32_t b0, uint32_t b1) {
    asm volatile("mma.sync.aligned.m16n8k16.row.col.f32.bf16.bf16.f32 "
                 "{%0,%1,%2,%3}, {%4,%5,%6,%7}, {%8,%9}, {%0,%1,%2,%3};"
                 : "+f"(d[0]), "+f"(d[1]), "+f"(d[2]), "+f"(d[3])
                 : "r"(a[0]), "r"(a[1]), "r"(a[2]), "r"(a[3]), "r"(b0), "r"(b1));
}
__device__ __forceinline__ void cpa16(uint32_t dst, const void* src) {
    asm volatile("cp.async.cg.shared.global [%0], [%1], 16;" :: "r"(dst), "l"(src));
}
#define CP_COMMIT() asm volatile("cp.async.commit_group;" ::: "memory")
#define CP_WAIT1()  asm volatile("cp.async.wait_group 1;" ::: "memory")

__device__ __forceinline__ uint32_t b2u(__nv_bfloat162 h) { return *reinterpret_cast<uint32_t*>(&h); }
__device__ __forceinline__ void split2(float a, float b, uint32_t& h, uint32_t& l) {
    __nv_bfloat162 hh = __floats2bfloat162_rn(a, b);
    float ra = __bfloat162float(hh.x), rb = __bfloat162float(hh.y);
    __nv_bfloat162 ll = __floats2bfloat162_rn(a - ra, b - rb);
    h = b2u(hh); l = b2u(ll);
}

// ---------------- prepass: fp32 K,V -> bf16 hi/lo scratch ----------------
__global__ __launch_bounds__(256)
void prepass(const float* __restrict__ Kg, const float* __restrict__ Vg)
{
    const size_t idx = (size_t)blockIdx.x * 256 + threadIdx.x;   // float4 index
    float4 k4 = ((const float4*)Kg)[idx];
    uint2 h, l;
    split2(k4.x, k4.y, h.x, l.x);
    split2(k4.z, k4.w, h.y, l.y);
    ((uint2*)gKH)[idx] = h;
    ((uint2*)gKL)[idx] = l;
    float4 v4 = ((const float4*)Vg)[idx];
    split2(v4.x, v4.y, h.x, l.x);
    split2(v4.z, v4.w, h.y, l.y);
    ((uint2*)gVH)[idx] = h;
    ((uint2*)gVL)[idx] = l;
}

// ---------------- main kernel ----------------
__global__ __launch_bounds__(NTH, 2)
void mha_mma(const float* __restrict__ Qg, const int* __restrict__ Mg,
             const float* __restrict__ QMg,
             float* __restrict__ Og, float* __restrict__ Ag)
{
    extern __shared__ char smem[];
    __shared__ float frow[QTILE];
    const uint32_t sb = smem_u32(smem);
    const int t = threadIdx.x;
    const int w = t >> 5, lane = t & 31;
    const int qr = w * 16;
    const int bb = blockIdx.y, q0 = blockIdx.x * QTILE;

    const size_t kvbase = (size_t)bb * TT * DKK;
    const __nv_bfloat16* srcs[4] = { gKH + kvbase, gKL + kvbase, gVH + kvbase, gVL + kvbase };

    // ---- Load Q tile (bf16 hi/lo, swizzled 128B rows) ----
    {
        const float4* Qg4 = (const float4*)(Qg + (size_t)(bb * TT + q0) * DKK);
        #pragma unroll
        for (int i = 0; i < 4; i++) {
            int g = t + i * NTH;                  // 0..511
            int row = g >> 3, u = g & 7;
            float4 a = Qg4[row * 16 + u * 2];
            float4 b = Qg4[row * 16 + u * 2 + 1];
            uint4 h, l;
            split2(a.x, a.y, h.x, l.x);
            split2(a.z, a.w, h.y, l.y);
            split2(b.x, b.y, h.z, l.z);
            split2(b.z, b.w, h.w, l.w);
            uint32_t off = row * 128 + ((u ^ (row & 7)) << 4);
            *(uint4*)(smem + OFF_Q + off) = h;
            *(uint4*)(smem + OFF_QLO + off) = l;
        }
    }

    // ---- prologue: prefetch chunks 0,1 ----
    #pragma unroll
    for (int s = 0; s < 2; s++) {
        uint32_t base = sb + OFF_ST0 + s * STAGE_SZ;
        #pragma unroll
        for (int i = 0; i < 16; i++) {
            int sel = i >> 2;
            int row = 16 * (i & 3) + (t >> 3);
            int u = t & 7;
            uint32_t dst = base + sel * BUF_SZ + row * 128 + ((u ^ (row & 7)) << 4);
            cpa16(dst, srcs[sel] + ((s * KCH + row) * DKK + u * 8));
        }
        CP_COMMIT();
    }
    __syncthreads();

    // ---- Preload Q A-fragments ----
    uint32_t qa_h[4][4], qa_l[4][4];
    {
        int qrow = qr + (lane & 15);
        #pragma unroll
        for (int s = 0; s < 4; s++) {
            int u = (2 * s + (lane >> 4)) ^ (qrow & 7);
            uint32_t addr = sb + OFF_Q + qrow * 128 + (u << 4);
            ldsm4(qa_h[s], addr);
            ldsm4(qa_l[s], addr + (OFF_QLO - OFF_Q));
        }
    }

    const int r0 = lane >> 2;
    const size_t grow0 = (size_t)(bb * TT + q0 + qr + r0);
    const size_t grow1 = grow0 + 8;
    float O[8][4];
    #pragma unroll
    for (int n = 0; n < 8; n++)
        #pragma unroll
        for (int i = 0; i < 4; i++) O[n][i] = 0.0f;
    float rs0 = 0.0f, rs1 = 0.0f;

    for (int c = 0; c < NCHUNK; c++) {
        CP_WAIT1();
        __syncthreads();
        const uint32_t sbase = sb + OFF_ST0 + (c & 1) * STAGE_SZ;

        // ---- Phase 1: S tiles + exp/mask/pack ----
        uint32_t pa_h[4][4], pa_l[4][4];
        const int* mb0 = Mg + grow0 * TT + c * KCH + (lane & 3) * 2;
        const int* mb1 = Mg + grow1 * TT + c * KCH + (lane & 3) * 2;
        float* ab0 = Ag + grow0 * TT + c * KCH + (lane & 3) * 2;
        float* ab1 = Ag + grow1 * TT + c * KCH + (lane & 3) * 2;

        #pragma unroll
        for (int j = 0; j < 8; j++) {
            float S[4] = {0.f, 0.f, 0.f, 0.f};
            uint32_t bh[8], bl[8];
            int krow = 8 * j + (lane & 7);
            int u0 = (lane >> 3) & 3;
            uint32_t a1 = sbase + krow * 128 + ((u0 ^ (krow & 7)) << 4);
            uint32_t a2 = sbase + krow * 128 + (((u0 + 4) ^ (krow & 7)) << 4);
            ldsm4(&bh[0], a1);
            ldsm4(&bh[4], a2);
            ldsm4(&bl[0], a1 + BUF_SZ);
            ldsm4(&bl[4], a2 + BUF_SZ);
            #pragma unroll
            for (int s = 0; s < 4; s++) {
                mma16816(S, qa_h[s], bh[s * 2], bh[s * 2 + 1]);
                mma16816(S, qa_h[s], bl[s * 2], bl[s * 2 + 1]);
                mma16816(S, qa_l[s], bh[s * 2], bh[s * 2 + 1]);
            }
            int2 m0 = *(const int2*)(mb0 + j * 8);
            int2 m1 = *(const int2*)(mb1 + j * 8);
            float e0 = m0.x ? 0.0f : __expf(S[0] * 0.125f);
            float e1 = m0.y ? 0.0f : __expf(S[1] * 0.125f);
            float e2 = m1.x ? 0.0f : __expf(S[2] * 0.125f);
            float e3 = m1.y ? 0.0f : __expf(S[3] * 0.125f);
            rs0 += e0 + e1; rs1 += e2 + e3;
            *(float2*)(ab0 + j * 8) = make_float2(e0, e1);
            *(float2*)(ab1 + j * 8) = make_float2(e2, e3);
            int s8 = j >> 1, i0 = (j & 1) * 2;
            split2(e0, e1, pa_h[s8][i0], pa_l[s8][i0]);
            split2(e2, e3, pa_h[s8][i0 + 1], pa_l[s8][i0 + 1]);
        }

        // ---- Phase 2: O += P @ V ----
        const uint32_t vbase = sbase + 2 * BUF_SZ;
        #pragma unroll
        for (int s = 0; s < 4; s++) {
            int vrow = 16 * s + (lane & 15);
            #pragma unroll
            for (int m = 0; m < 4; m++) {
                int u = ((lane >> 4) + m * 2) ^ (vrow & 7);
                uint32_t av = vbase + vrow * 128 + (u << 4);
                uint32_t vh[4], vl[4];
                ldsm4t(vh, av);
                ldsm4t(vl, av + BUF_SZ);
                mma16816(O[2 * m],     pa_h[s], vh[0], vh[1]);
                mma16816(O[2 * m],     pa_h[s], vl[0], vl[1]);
                mma16816(O[2 * m],     pa_l[s], vh[0], vh[1]);
                mma16816(O[2 * m + 1], pa_h[s], vh[2], vh[3]);
                mma16816(O[2 * m + 1], pa_h[s], vl[2], vl[3]);
                mma16816(O[2 * m + 1], pa_l[s], vh[2], vh[3]);
            }
        }

        // ---- prefetch chunk c+2 into the buffer we just consumed ----
        __syncthreads();
        if (c + 2 < NCHUNK) {
            uint32_t base = sb + OFF_ST0 + (c & 1) * STAGE_SZ;
            #pragma unroll
            for (int i = 0; i < 16; i++) {
                int sel = i >> 2;
                int row = 16 * (i & 3) + (t >> 3);
                int u = t & 7;
                uint32_t dst = base + sel * BUF_SZ + row * 128 + ((u ^ (row & 7)) << 4);
                cpa16(dst, srcs[sel] + (((c + 2) * KCH + row) * DKK + u * 8));
            }
        }
        CP_COMMIT();
    }

    // ---- row sums (quad reduction), scale factors ----
    rs0 += __shfl_xor_sync(0xFFFFFFFFu, rs0, 1);
    rs0 += __shfl_xor_sync(0xFFFFFFFFu, rs0, 2);
    rs1 += __shfl_xor_sync(0xFFFFFFFFu, rs1, 1);
    rs1 += __shfl_xor_sync(0xFFFFFFFFu, rs1, 2);
    float f0 = QMg[grow0] / rs0;
    float f1 = QMg[grow1] / rs1;

    // ---- O output ----
    {
        float2* o0 = (float2*)(Og + grow0 * DKK + (lane & 3) * 2);
        float2* o1 = (float2*)(Og + grow1 * DKK + (lane & 3) * 2);
        #pragma unroll
        for (int n = 0; n < 8; n++) {
            o0[n * 4] = make_float2(f0 * O[n][0], f0 * O[n][1]);
            o1[n * 4] = make_float2(f1 * O[n][2], f1 * O[n][3]);
        }
    }

    // ---- in-kernel attn rescale ----
    if ((lane & 3) == 0) {
        frow[qr + r0] = f0;
        frow[qr + r0 + 8] = f1;
    }
    __syncthreads();
    {
        float4* A4 = (float4*)(Ag + ((size_t)bb * TT + q0) * TT);
        #pragma unroll 4
        for (int i = 0; i < 128; i++) {
            int idx = i * NTH + t;                // 0..16383
            float f = frow[idx >> 8];
            float4 v = A4[idx];
            v.x *= f; v.y *= f; v.z *= f; v.w *= f;
            A4[idx] = v;
        }
    }
}

extern "C" void kernel_launch(void* const* d_in, const int* in_sizes, int n_in,
                              void* d_out, int out_size) {
    int mask_i = 3, qm_i = 4;
    for (int i = 0; i < n_in; i++) {
        if (in_sizes[i] == BB * TT * TT) mask_i = i;
        else if (in_sizes[i] == BB * TT) qm_i = i;
    }
    int k_i = 0, v_i = 1, q_i = 2;
    if (mask_i == 1 && qm_i == 3) { k_i = 0; q_i = 2; v_i = 4; }

    const float* Kg  = (const float*)d_in[k_i];
    const float* Vg  = (const float*)d_in[v_i];
    const float* Qg  = (const float*)d_in[q_i];
    const int*   Mg  = (const int*)d_in[mask_i];
    const float* QMg = (const float*)d_in[qm_i];

    float* Og = (float*)d_out;
    float* Ag = (float*)d_out + (size_t)BB * TT * DKK;

    prepass<<<(BB * TT * DKK / 4) / 256, 256>>>(Kg, Vg);

    cudaFuncSetAttribute(mha_mma, cudaFuncAttributeMaxDynamicSharedMemorySize, SMEM_TOTAL);
    dim3 grid(TT / QTILE, BB);
    mha_mma<<<grid, NTH, SMEM_TOTAL>>>(Qg, Mg, QMg, Og, Ag);
}